// round 17
// baseline (speedup 1.0000x reference)
#include <cuda_runtime.h>
#include <cstdint>

#define Bq  256
#define Mq  512
#define Nq  8192
#define TMq 1024
#define NSPLIT 8
#define GSPLIT 2
#define CSPLIT 4

#define BM 128
#define BN 64
#define BK 16
#define LDK2 20                 // float2 per row: 16 data + 4 pad (160B row)
#define A_F2 (BM*LDK2)          // 2560 float2
#define B_F2 (BN*LDK2)          // 1280 float2
#define STG_F2 (A_F2+B_F2)      // 3840 float2 per stage
#define STG_B (STG_F2*8)        // 30720 bytes
#define NSTAGE 3
#define SMEM_TOT (NSTAGE*STG_B) // 92160 bytes

// ---------------- device scratch (hi/lo interleaved as float2) ----------------
__device__ float2 g_A2 [(size_t)2*Mq*Nq];      // P = [Ar;Ai], K-major, (h,l)
__device__ float2 g_AT2[(size_t)Nq*TMq];       // A^T rows n, LD 1024
__device__ float2 g_rn2[(size_t)2*Bq*Nq];      // r_n as 512 rows x 8192
__device__ float2 g_S2 [TMq*TMq];
__device__ float2 g_X2 [TMq*TMq];
__device__ float2 g_T1t2[TMq*TMq];             // (S@X)^T
__device__ float2 g_V2 [Bq*TMq];               // z-u-Arn
__device__ float2 g_Tm2[Bq*TMq];               // w
__device__ float2 g_x2 [Bq*Nq];
// plain fp32
__device__ float g_Gpart[GSPLIT][TMq*TMq];
__device__ float g_S[TMq*TMq], g_X[TMq*TMq], g_T2[TMq*TMq];
__device__ float g_C12p[CSPLIT][2*Bq*TMq];
__device__ float g_Arn[Bq*TMq];
__device__ float g_x[Bq*Nq];
__device__ float g_z[Bq*TMq], g_u[Bq*TMq];
__device__ float g_part[NSPLIT][Bq*TMq];
__device__ float g_v[TMq], g_w[TMq], g_lam[1];

__device__ __forceinline__ float load_rho(const float* p){
    float v = *p; v = fminf(5.f, fmaxf(-5.f, v)); return expf(v);
}
__device__ __forceinline__ float load_eps(const float* p){
    float v = *p; v = fminf(0.f, fmaxf(-5.f, v)); return expf(v);
}
__device__ __forceinline__ uint32_t f2tf(float v){
    uint32_t r; asm("cvt.rna.tf32.f32 %0, %1;" : "=r"(r) : "f"(v)); return r;
}
__device__ __forceinline__ float2 split2(float v){
    float h = __uint_as_float(f2tf(v));
    float l = __uint_as_float(f2tf(v - h));
    return make_float2(h, l);
}
__device__ __forceinline__ void mma8(float* c, const uint32_t* a, const uint32_t* b){
    asm volatile("mma.sync.aligned.m16n8k8.row.col.f32.tf32.tf32.f32 "
        "{%0,%1,%2,%3}, {%4,%5,%6,%7}, {%8,%9}, {%0,%1,%2,%3};\n"
        : "+f"(c[0]),"+f"(c[1]),"+f"(c[2]),"+f"(c[3])
        : "r"(a[0]),"r"(a[1]),"r"(a[2]),"r"(a[3]), "r"(b[0]),"r"(b[1]));
}
__device__ __forceinline__ void cpa16(uint32_t saddr, const void* g){
    asm volatile("cp.async.ca.shared.global [%0], [%1], 16;" :: "r"(saddr), "l"(g));
}

// one BK=16 stage of 3xTF32 mma; fragments via 64-bit LDS ((h,l) pairs)
__device__ __forceinline__ void mma_stage(const float2* sA, const float2* sB,
                                          float acc[2][4][4], int wm,int wn,int qr,int qc){
    #pragma unroll
    for(int k8=0;k8<BK;k8+=8){
        uint32_t ah[2][4], al[2][4], bh[4][2], bl[4][2];
        #pragma unroll
        for(int mt=0;mt<2;mt++){
            int m = wm*32 + mt*16;
            float2 p0 = sA[(m+qr  )*LDK2 + k8+qc  ];
            float2 p1 = sA[(m+qr+8)*LDK2 + k8+qc  ];
            float2 p2 = sA[(m+qr  )*LDK2 + k8+qc+4];
            float2 p3 = sA[(m+qr+8)*LDK2 + k8+qc+4];
            ah[mt][0]=__float_as_uint(p0.x); al[mt][0]=__float_as_uint(p0.y);
            ah[mt][1]=__float_as_uint(p1.x); al[mt][1]=__float_as_uint(p1.y);
            ah[mt][2]=__float_as_uint(p2.x); al[mt][2]=__float_as_uint(p2.y);
            ah[mt][3]=__float_as_uint(p3.x); al[mt][3]=__float_as_uint(p3.y);
        }
        #pragma unroll
        for(int nt=0;nt<4;nt++){
            int n = wn*32 + nt*8;
            float2 q0 = sB[(n+qr)*LDK2 + k8+qc  ];
            float2 q1 = sB[(n+qr)*LDK2 + k8+qc+4];
            bh[nt][0]=__float_as_uint(q0.x); bl[nt][0]=__float_as_uint(q0.y);
            bh[nt][1]=__float_as_uint(q1.x); bl[nt][1]=__float_as_uint(q1.y);
        }
        #pragma unroll
        for(int mt=0;mt<2;mt++)
            #pragma unroll
            for(int nt=0;nt<4;nt++){
                mma8(acc[mt][nt], ah[mt], bh[nt]);
                mma8(acc[mt][nt], ah[mt], bl[nt]);
                mma8(acc[mt][nt], al[mt], bh[nt]);
            }
    }
}

#define GEMM_PRE() \
    extern __shared__ float2 smem[]; \
    uint32_t sbase = (uint32_t)__cvta_generic_to_shared(smem); \
    float acc[2][4][4] = {}; \
    const int tid=threadIdx.x, lane=tid&31, wid=tid>>5; \
    const int wm=wid&3, wn=wid>>2, qr=lane>>2, qc=lane&3;

// issue one stage's cp.async set from pre-advanced pointers, then advance by BK
#define ISSUE_STAGE(BUF) do{ \
    uint32_t _sb = sbase + (uint32_t)(BUF)*STG_B; \
    _Pragma("unroll") for(int _i=0;_i<4;_i++){ cpa16(_sb + sa_[_i], ga_[_i]); ga_[_i]+=BK; } \
    _Pragma("unroll") for(int _i=0;_i<2;_i++){ cpa16(_sb + sb_[_i], gb_[_i]); gb_[_i]+=BK; } \
    asm volatile("cp.async.commit_group;"); \
}while(0)

// 3-stage pipeline, one barrier per K-stage, pointer-increment loaders
#define GEMM_LOOP(A2P,LDA,B2P,LDB,KBEG,KEND) do{ \
    const int nst = ((KEND)-(KBEG))/BK; \
    const float2* ga_[4]; uint32_t sa_[4]; \
    const float2* gb_[2]; uint32_t sb_[2]; \
    _Pragma("unroll") for(int _i=0;_i<4;_i++){ \
        int _idx = tid + _i*256; int _m = _idx>>3; int _c = _idx&7; \
        ga_[_i] = (A2P) + (size_t)(m0+_m)*(LDA) + (KBEG) + _c*2; \
        sa_[_i] = (uint32_t)((_m*LDK2 + _c*2)*8); \
    } \
    _Pragma("unroll") for(int _i=0;_i<2;_i++){ \
        int _idx = tid + _i*256; int _m = _idx>>3; int _c = _idx&7; \
        gb_[_i] = (B2P) + (size_t)(n0+_m)*(LDB) + (KBEG) + _c*2; \
        sb_[_i] = (uint32_t)(A_F2*8 + (_m*LDK2 + _c*2)*8); \
    } \
    ISSUE_STAGE(0); \
    ISSUE_STAGE(1); \
    int bufc = 2, bufr = 0; \
    for(int s=0;s<nst;s++){ \
        if(s < nst-1){ asm volatile("cp.async.wait_group 1;"); } \
        else        { asm volatile("cp.async.wait_group 0;"); } \
        __syncthreads(); \
        if(s+2 < nst){ \
            ISSUE_STAGE(bufc); \
            bufc++; if(bufc==NSTAGE) bufc=0; \
        } \
        const float2* st_ = smem + bufr*STG_F2; \
        bufr++; if(bufr==NSTAGE) bufr=0; \
        mma_stage(st_, st_+A_F2, acc, wm, wn, qr, qc); \
    } \
}while(0)

#define EPILOG(...) \
    _Pragma("unroll") for(int mt=0;mt<2;mt++) \
    _Pragma("unroll") for(int nt=0;nt<4;nt++) \
    _Pragma("unroll") for(int ci=0;ci<4;ci++){ \
        int m = m0 + wm*32 + mt*16 + qr + ((ci>>1)<<3); \
        int n = n0 + wn*32 + nt*8 + (qc<<1) + (ci&1); \
        float v = acc[mt][nt][ci]; __VA_ARGS__; }

// ---------------- split precompute kernels ----------------
__global__ void k_splitA(const float* __restrict__ A){
    int idx = blockIdx.x*256 + threadIdx.x;
    if(idx >= 2*Mq*Nq/4) return;
    float4 v = ((const float4*)A)[idx];
    float2 a = split2(v.x), b = split2(v.y), c = split2(v.z), d = split2(v.w);
    float4* dst = (float4*)g_A2;
    dst[2*idx  ] = make_float4(a.x,a.y,b.x,b.y);
    dst[2*idx+1] = make_float4(c.x,c.y,d.x,d.y);
}
__global__ void k_split_rn(const float* __restrict__ rn){
    int idx = blockIdx.x*256 + threadIdx.x;
    if(idx >= Bq*2*Nq/4) return;
    float4 v = ((const float4*)rn)[idx];
    float2 a = split2(v.x), b = split2(v.y), c = split2(v.z), d = split2(v.w);
    float4* dst = (float4*)g_rn2;
    dst[2*idx  ] = make_float4(a.x,a.y,b.x,b.y);
    dst[2*idx+1] = make_float4(c.x,c.y,d.x,d.y);
}
// transpose A (1024 x 8192) -> AT (8192 x 1024), split
__global__ void k_splitAT(const float* __restrict__ A){
    __shared__ float t[32][33];
    int x = blockIdx.x*32 + threadIdx.x;      // col n
    int y = blockIdx.y*32 + threadIdx.y;      // row p
    #pragma unroll
    for(int j=0;j<32;j+=8)
        t[threadIdx.y+j][threadIdx.x] = A[(size_t)(y+j)*Nq + x];
    __syncthreads();
    int xo = blockIdx.y*32 + threadIdx.x;     // p
    int yo = blockIdx.x*32 + threadIdx.y;     // n
    #pragma unroll
    for(int j=0;j<32;j+=8)
        g_AT2[(size_t)(yo+j)*TMq + xo] = split2(t[threadIdx.x][threadIdx.y+j]);
}

// ---------------- C12 = rn(512 rows) @ P^T, split-K ----------------
__global__ __launch_bounds__(256) void k_C12(){
    GEMM_PRE();
    const int n0 = blockIdx.x*BN, m0 = blockIdx.y*BM;
    const int kb = blockIdx.z*(Nq/CSPLIT);
    GEMM_LOOP(g_rn2,Nq, g_A2,Nq, kb, kb+Nq/CSPLIT);
    EPILOG( g_C12p[blockIdx.z][(size_t)m*TMq + n] = v )
}
__global__ void k_Arn_combine(){
    int idx = blockIdx.x*256 + threadIdx.x;
    if(idx >= Bq*Mq) return;
    int b = idx >> 9, m = idx & 511;
    float c1m=0,c1s=0,c2m=0,c2s=0;
    #pragma unroll
    for(int z=0;z<CSPLIT;z++){
        c1m += g_C12p[z][(size_t)(2*b  )*TMq + m];
        c1s += g_C12p[z][(size_t)(2*b  )*TMq + 512 + m];
        c2m += g_C12p[z][(size_t)(2*b+1)*TMq + m];
        c2s += g_C12p[z][(size_t)(2*b+1)*TMq + 512 + m];
    }
    g_Arn[(size_t)b*TMq + m]       = c1m - c2s;
    g_Arn[(size_t)b*TMq + 512 + m] = c2m + c1s;
}

// ---------------- G = P @ P^T (split-K 2) ----------------
__global__ __launch_bounds__(256) void k_G(){
    GEMM_PRE();
    const int n0 = blockIdx.x*BN, m0 = blockIdx.y*BM;
    const int kb = blockIdx.z*(Nq/GSPLIT);
    GEMM_LOOP(g_A2,Nq, g_A2,Nq, kb, kb+Nq/GSPLIT);
    EPILOG( g_Gpart[blockIdx.z][(size_t)m*TMq + n] = v )
}
__global__ void k_S_from_G(const float* __restrict__ log_rho){
    int idx = blockIdx.x*256 + threadIdx.x;
    if(idx >= Mq*Mq) return;
    int i = idx/Mq, j = idx%Mq;
    float g00=0,g01=0,g10=0,g11=0;
    #pragma unroll
    for(int z=0;z<GSPLIT;z++){
        g00 += g_Gpart[z][(size_t)i*TMq + j];
        g01 += g_Gpart[z][(size_t)i*TMq + 512 + j];
        g10 += g_Gpart[z][(size_t)(512+i)*TMq + j];
        g11 += g_Gpart[z][(size_t)(512+i)*TMq + 512 + j];
    }
    float rho = load_rho(log_rho);
    float sr = g00 + g11 + ((i==j) ? 1.0f/(rho+1e-12f) : 0.0f);
    float si = g10 - g01;
    size_t i00 = (size_t)i*TMq + j,        i01 = (size_t)i*TMq + 512 + j;
    size_t i10 = (size_t)(512+i)*TMq + j,  i11 = (size_t)(512+i)*TMq + 512 + j;
    float2 sp = split2(sr), sn = split2(-si), spp = split2(si);
    g_S[i00]=sr;  g_S2[i00]=sp;
    g_S[i11]=sr;  g_S2[i11]=sp;
    g_S[i01]=-si; g_S2[i01]=sn;
    g_S[i10]=si;  g_S2[i10]=spp;
}

// ---------------- power iteration ----------------
__global__ void k_pow_init(){
    int i = blockIdx.x*256 + threadIdx.x;
    if(i < TMq) g_v[i] = 1.0f + 0.001f*(float)i;
}
__global__ void k_pow_mv(){
    int row = blockIdx.x;
    float s = 0.f;
    for(int j=threadIdx.x;j<TMq;j+=256) s += g_S[(size_t)row*TMq + j]*g_v[j];
    __shared__ float red[256];
    red[threadIdx.x] = s; __syncthreads();
    for(int o=128;o>0;o>>=1){ if(threadIdx.x<o) red[threadIdx.x]+=red[threadIdx.x+o]; __syncthreads(); }
    if(threadIdx.x==0) g_w[row] = red[0];
}
__global__ void k_pow_norm(){
    __shared__ float red[1024];
    int tid = threadIdx.x;
    float w = g_w[tid];
    red[tid] = w*w; __syncthreads();
    for(int o=512;o>0;o>>=1){ if(tid<o) red[tid]+=red[tid+o]; __syncthreads(); }
    float nn = sqrtf(red[0]);
    g_v[tid] = g_w[tid]/nn;
    if(tid==0) g_lam[0] = nn;
}
__global__ void k_X_init(const float* __restrict__ log_rho){
    int idx = blockIdx.x*256 + threadIdx.x;
    if(idx >= TMq*TMq) return;
    int i = idx/TMq, j = idx%TMq;
    float rho = load_rho(log_rho);
    float c = (i==j) ? 2.0f/(1.1f*g_lam[0] + 1.0f/(rho + 1e-12f)) : 0.0f;
    g_X[idx] = c; g_X2[idx] = split2(c);
}

// ---------------- Newton GEMMs ----------------
// T1t = (S @ X)^T  (X symmetric -> B-side reads X rows)
__global__ __launch_bounds__(256) void k_T1(){
    GEMM_PRE();
    const int n0 = blockIdx.x*BN, m0 = blockIdx.y*BM;
    GEMM_LOOP(g_S2,TMq, g_X2,TMq, 0, TMq);
    EPILOG( g_T1t2[(size_t)n*TMq + m] = split2(v) )
}
// T2 = X @ T1 = X @ (T1t)^T
__global__ __launch_bounds__(256) void k_T2(){
    GEMM_PRE();
    const int n0 = blockIdx.x*BN, m0 = blockIdx.y*BM;
    GEMM_LOOP(g_X2,TMq, g_T1t2,TMq, 0, TMq);
    EPILOG( g_T2[(size_t)m*TMq + n] = v )
}
__global__ void k_newton_upd(){
    int idx = blockIdx.x*256 + threadIdx.x;
    if(idx >= TMq*TMq) return;
    int i = idx/TMq, j = idx%TMq;
    float v = 2.0f*g_X[idx] - 0.5f*(g_T2[idx] + g_T2[(size_t)j*TMq + i]);
    g_X[idx] = v; g_X2[idx] = split2(v);
}

// ---------------- ADMM loop ----------------
__global__ void k_init_V(const float* __restrict__ y, const float* __restrict__ u_in){
    int idx = blockIdx.x*256 + threadIdx.x;
    if(idx >= Bq*TMq) return;
    float zz = y[idx], uu = u_in[idx];
    g_z[idx] = zz; g_u[idx] = uu;
    g_V2[idx] = split2(zz - uu - g_Arn[idx]);
}
// w = V @ X  -> Tm split
__global__ __launch_bounds__(256) void k_w(const int* __restrict__ ns, int step){
    if(ns && step >= *ns) return;
    GEMM_PRE();
    const int n0 = blockIdx.x*BN, m0 = blockIdx.y*BM;
    GEMM_LOOP(g_V2,TMq, g_X2,TMq, 0, TMq);
    EPILOG( g_Tm2[(size_t)m*TMq + n] = split2(v) )
}
// x = relu(rn_r + w @ A)  (B-side = AT rows)
__global__ __launch_bounds__(256) void k_x(const float* __restrict__ r_n,
                                           const int* __restrict__ ns, int step){
    if(ns && step >= *ns) return;
    GEMM_PRE();
    const int n0 = blockIdx.x*BN, m0 = blockIdx.y*BM;
    GEMM_LOOP(g_Tm2,TMq, g_AT2,TMq, 0, TMq);
    EPILOG( float xv = fmaxf(0.0f, r_n[(size_t)m*2*Nq + n] + v);
            g_x[(size_t)m*Nq + n] = xv;
            g_x2[(size_t)m*Nq + n] = split2(xv) )
}
// Ax partials = x @ P^T, split-K 8
__global__ __launch_bounds__(256) void k_Ax(const int* __restrict__ ns, int step){
    if(ns && step >= *ns) return;
    GEMM_PRE();
    const int n0 = blockIdx.x*BN, m0 = blockIdx.y*BM;
    const int kb = blockIdx.z*(Nq/NSPLIT);
    GEMM_LOOP(g_x2,Nq, g_A2,Nq, kb, kb+Nq/NSPLIT);
    EPILOG( g_part[blockIdx.z][(size_t)m*TMq + n] = v )
}
// d = Ax + u - y; z,u update; V = z-u-Arn split
__global__ void k_zu(const float* __restrict__ y,
                     const float* __restrict__ log_eps,
                     const int* __restrict__ ns, int step){
    if(ns && step >= *ns) return;
    int b = blockIdx.x;
    float d0[4]; float s = 0.f;
    #pragma unroll
    for(int j=0;j<4;j++){
        int p = threadIdx.x + 256*j;
        size_t q = (size_t)b*TMq + p;
        float ax = 0.f;
        #pragma unroll
        for(int ks=0;ks<NSPLIT;ks++) ax += g_part[ks][q];
        float d = ax + g_u[q] - y[q];
        d0[j] = d; s += d*d;
    }
    __shared__ float red[256];
    red[threadIdx.x] = s; __syncthreads();
    for(int o=128;o>0;o>>=1){ if(threadIdx.x<o) red[threadIdx.x]+=red[threadIdx.x+o]; __syncthreads(); }
    float nrm = sqrtf(red[0]);
    float eps = load_eps(log_eps);
    float scale = fminf(1.0f, eps/fmaxf(nrm, 1e-12f));
    #pragma unroll
    for(int j=0;j<4;j++){
        int p = threadIdx.x + 256*j;
        size_t q = (size_t)b*TMq + p;
        float zz = y[q] + scale*d0[j];
        float uu = (1.0f - scale)*d0[j];
        g_z[q] = zz; g_u[q] = uu;
        g_V2[q] = split2(zz - uu - g_Arn[q]);
    }
}

__global__ void k_writeout(float* __restrict__ out){
    int idx = blockIdx.x*256 + threadIdx.x;
    const int xtot = Bq*2*Nq;
    const int total = xtot + Bq*TMq;
    if(idx >= total) return;
    if(idx < xtot){
        int b = idx / (2*Nq); int rem = idx - b*2*Nq;
        out[idx] = (rem < Nq) ? g_x[(size_t)b*Nq + rem] : 0.0f;
    }else{
        out[idx] = g_u[idx - xtot];
    }
}

// ---------------- host ----------------
extern "C" void kernel_launch(void* const* d_in, const int* in_sizes, int n_in,
                              void* d_out, int out_size){
    const float* r_n     = (const float*)d_in[0];
    const float* y       = (const float*)d_in[1];
    const float* u_in    = (const float*)d_in[2];
    const float* A       = (const float*)d_in[3];
    const float* log_rho = (const float*)d_in[4];
    const float* log_eps = (const float*)d_in[5];
    const int*   ns      = (n_in > 6) ? (const int*)d_in[6] : nullptr;

    static bool attr_done = false;
    if(!attr_done){
        cudaFuncSetAttribute(k_C12, cudaFuncAttributeMaxDynamicSharedMemorySize, SMEM_TOT);
        cudaFuncSetAttribute(k_G,   cudaFuncAttributeMaxDynamicSharedMemorySize, SMEM_TOT);
        cudaFuncSetAttribute(k_T1,  cudaFuncAttributeMaxDynamicSharedMemorySize, SMEM_TOT);
        cudaFuncSetAttribute(k_T2,  cudaFuncAttributeMaxDynamicSharedMemorySize, SMEM_TOT);
        cudaFuncSetAttribute(k_w,   cudaFuncAttributeMaxDynamicSharedMemorySize, SMEM_TOT);
        cudaFuncSetAttribute(k_x,   cudaFuncAttributeMaxDynamicSharedMemorySize, SMEM_TOT);
        cudaFuncSetAttribute(k_Ax,  cudaFuncAttributeMaxDynamicSharedMemorySize, SMEM_TOT);
        attr_done = true;
    }

    // operand splits
    k_splitA  <<<(2*Mq*Nq/4 + 255)/256, 256>>>(A);
    k_splitAT <<<dim3(Nq/32, TMq/32), dim3(32,8)>>>(A);
    k_split_rn<<<(Bq*2*Nq/4 + 255)/256, 256>>>(r_n);

    // Arn = A @ r_n
    k_C12<<<dim3(TMq/BN, 512/BM, CSPLIT), 256, SMEM_TOT>>>();
    k_Arn_combine<<<(Bq*Mq + 255)/256, 256>>>();

    // G = P P^T
    k_G<<<dim3(TMq/BN, TMq/BM, GSPLIT), 256, SMEM_TOT>>>();
    k_S_from_G<<<(Mq*Mq + 255)/256, 256>>>(log_rho);

    // power iteration
    k_pow_init<<<(TMq+255)/256, 256>>>();
    for(int i=0;i<8;i++){
        k_pow_mv<<<TMq, 256>>>();
        k_pow_norm<<<1, 1024>>>();
    }

    // Newton-Schulz (6 iters, symmetrized)
    k_X_init<<<(TMq*TMq + 255)/256, 256>>>(log_rho);
    for(int i=0;i<6;i++){
        k_T1<<<dim3(TMq/BN, TMq/BM), 256, SMEM_TOT>>>();
        k_T2<<<dim3(TMq/BN, TMq/BM), 256, SMEM_TOT>>>();
        k_newton_upd<<<(TMq*TMq + 255)/256, 256>>>();
    }

    // ADMM loop
    k_init_V<<<(Bq*TMq + 255)/256, 256>>>(y, u_in);
    for(int step=0;step<5;step++){
        k_w <<<dim3(TMq/BN, Bq/BM),          256, SMEM_TOT>>>(ns, step);
        k_x <<<dim3(Nq/BN,  Bq/BM),          256, SMEM_TOT>>>(r_n, ns, step);
        k_Ax<<<dim3(TMq/BN, Bq/BM, NSPLIT),  256, SMEM_TOT>>>(ns, step);
        k_zu<<<Bq, 256>>>(y, log_eps, ns, step);
    }

    k_writeout<<<(Bq*2*Nq + Bq*TMq + 255)/256, 256>>>((float*)d_out);
}